// round 1
// baseline (speedup 1.0000x reference)
#include <cuda_runtime.h>
#include <math.h>

// ---------------- problem constants ----------------
#define HW     16384      // 128*128
#define WIMG   128
#define C_IN   192
#define C3     576        // 3*C_IN
#define NB     8          // batch
#define HEADS  8
#define HD     24         // C_IN / HEADS

// ---------------- scratch (static device memory; no allocs) ----------------
// [s*8+b][ch][n]  -- s: 0=rgb, 1=ir
__device__ float g_y  [16][C3 * HW];   // after 1x1 qkv conv        (~604 MB)
__device__ float g_qkv[16][C3 * HW];   // after depthwise 3x3        (~604 MB)
// combo t: t=0 -> out_rgb (attn_rgb = softmax(iq . rk^T)), t=1 -> out_ir (rq . ik^T)
__device__ float g_S  [2][NB][HEADS][HD * HD];  // unnormalized gram
__device__ float g_qss[2][NB][HEADS][HD];       // sum of squares of q rows (of that combo)
__device__ float g_kss[2][NB][HEADS][HD];       // sum of squares of k rows
__device__ float g_M  [2][NB][C_IN * C_IN];     // fused  wproj @ blockdiag(attn)

// ---------------- K0: zero the atomic accumulators ----------------
__global__ void k0_zero() {
    int idx = blockIdx.x * 256 + threadIdx.x;
    const int nS = 2 * NB * HEADS * HD * HD;     // 73728
    const int nN = 2 * NB * HEADS * HD;          // 3072
    if (idx < nS) (&g_S[0][0][0][0])[idx] = 0.f;
    if (idx < nN) {
        (&g_qss[0][0][0][0])[idx] = 0.f;
        (&g_kss[0][0][0][0])[idx] = 0.f;
    }
}

// ---------------- shared GEMM tile: C[m0:m0+64, n0:n0+128] += A[.,192] * B[192, HW] ----------------
// A row-major, row stride 192.  B row stride HW.  256 threads.
__device__ __forceinline__ void gemm_64x128(
    const float* __restrict__ A,
    const float* __restrict__ Bm,
    float* __restrict__ C,
    int m0, int n0)
{
    __shared__ float As[16][65];    // padded: conflict-free transposed store
    __shared__ float Bs[16][128];

    const int tid = threadIdx.x;
    const int tm  = (tid >> 4) * 4;        // 0..60
    const int tn  = (tid & 15) * 8;        // 0..120

    const int lam = tid >> 2;              // A load: m row   (0..63)
    const int lak = (tid & 3) * 4;         // A load: k quad
    const int lbk = tid >> 4;              // B load: k row   (0..15)
    const int lbn = (tid & 15) * 8;        // B load: n offset

    float acc[4][8];
#pragma unroll
    for (int i = 0; i < 4; i++)
#pragma unroll
        for (int j = 0; j < 8; j++) acc[i][j] = 0.f;

    for (int k0 = 0; k0 < 192; k0 += 16) {
        float4 av = *(const float4*)&A[(size_t)(m0 + lam) * 192 + k0 + lak];
        float4 b0 = *(const float4*)&Bm[(size_t)(k0 + lbk) * HW + n0 + lbn];
        float4 b1 = *(const float4*)&Bm[(size_t)(k0 + lbk) * HW + n0 + lbn + 4];

        As[lak + 0][lam] = av.x;
        As[lak + 1][lam] = av.y;
        As[lak + 2][lam] = av.z;
        As[lak + 3][lam] = av.w;
        *(float4*)&Bs[lbk][lbn]     = b0;
        *(float4*)&Bs[lbk][lbn + 4] = b1;
        __syncthreads();

#pragma unroll
        for (int kk = 0; kk < 16; kk++) {
            float a0 = As[kk][tm + 0];
            float a1 = As[kk][tm + 1];
            float a2 = As[kk][tm + 2];
            float a3 = As[kk][tm + 3];
            float4 q0 = *(const float4*)&Bs[kk][tn];
            float4 q1 = *(const float4*)&Bs[kk][tn + 4];
            float bb[8] = {q0.x, q0.y, q0.z, q0.w, q1.x, q1.y, q1.z, q1.w};
#pragma unroll
            for (int j = 0; j < 8; j++) {
                acc[0][j] += a0 * bb[j];
                acc[1][j] += a1 * bb[j];
                acc[2][j] += a2 * bb[j];
                acc[3][j] += a3 * bb[j];
            }
        }
        __syncthreads();
    }

#pragma unroll
    for (int i = 0; i < 4; i++) {
        float4 o0 = make_float4(acc[i][0], acc[i][1], acc[i][2], acc[i][3]);
        float4 o1 = make_float4(acc[i][4], acc[i][5], acc[i][6], acc[i][7]);
        *(float4*)&C[(size_t)(m0 + tm + i) * HW + n0 + tn]     = o0;
        *(float4*)&C[(size_t)(m0 + tm + i) * HW + n0 + tn + 4] = o1;
    }
}

// ---------------- K1: 1x1 qkv conv, y = w_qkv(576x192) @ x(192xHW), per (s,b) ----------------
__global__ void k1_qkv(const float* __restrict__ rgb,
                       const float* __restrict__ ir,
                       const float* __restrict__ wqkv)
{
    int z = blockIdx.z;                   // s*8+b
    int s = z >> 3, b = z & 7;
    const float* x = (s ? ir : rgb) + (size_t)b * C_IN * HW;
    gemm_64x128(wqkv, x, g_y[z], blockIdx.y * 64, blockIdx.x * 128);
}

// ---------------- K2: depthwise 3x3 SAME, per channel ----------------
__global__ void k2_dw(const float* __restrict__ wdw)
{
    int z  = blockIdx.z;                  // s*8+b
    int ch = blockIdx.y;                  // 0..575
    int n  = blockIdx.x * 256 + threadIdx.x;
    const float* yin = g_y[z]  + (size_t)ch * HW;
    float*       out = g_qkv[z] + (size_t)ch * HW;

    const float* w = wdw + ch * 9;
    float w00 = w[0], w01 = w[1], w02 = w[2];
    float w10 = w[3], w11 = w[4], w12 = w[5];
    float w20 = w[6], w21 = w[7], w22 = w[8];

    int yy = n >> 7, xx = n & 127;
    float acc = 0.f;
    bool xm = (xx > 0), xp = (xx < WIMG - 1);
    if (yy > 0) {
        const float* r = yin + (size_t)(yy - 1) * WIMG;
        if (xm) acc += w00 * r[xx - 1];
        acc += w01 * r[xx];
        if (xp) acc += w02 * r[xx + 1];
    }
    {
        const float* r = yin + (size_t)yy * WIMG;
        if (xm) acc += w10 * r[xx - 1];
        acc += w11 * r[xx];
        if (xp) acc += w12 * r[xx + 1];
    }
    if (yy < WIMG - 1) {
        const float* r = yin + (size_t)(yy + 1) * WIMG;
        if (xm) acc += w20 * r[xx - 1];
        acc += w21 * r[xx];
        if (xp) acc += w22 * r[xx + 1];
    }
    out[n] = acc;
}

// ---------------- K3: channel Gram S = q . k^T (24x24 per (t,b,h)) + row sumsq ----------------
// combo t=0: q = iq (s=1), k = rk (s=0);  t=1: q = rq (s=0), k = ik (s=1)
__global__ void k3_gram()
{
    int t  = blockIdx.z;
    int bh = blockIdx.y;
    int b = bh >> 3, h = bh & 7;
    int n0 = blockIdx.x * 1024;           // 16 segments of 1024

    int qs = (t == 0) ? 1 : 0;
    int ks = 1 - qs;
    const float* qbase = g_qkv[qs * 8 + b] + (size_t)(h * HD) * HW;          // q channels
    const float* kbase = g_qkv[ks * 8 + b] + (size_t)(C_IN + h * HD) * HW;   // k channels

    __shared__ float qsm[HD][133];
    __shared__ float ksm[HD][133];

    int tid = threadIdx.x;                // 576 = 24*24
    int c = tid / HD, d = tid % HD;

    float acc = 0.f, ssq = 0.f, ssk = 0.f;
    for (int ch0 = 0; ch0 < 1024; ch0 += 128) {
        __syncthreads();
        for (int i = tid; i < HD * 128; i += 576) {
            int r = i >> 7, col = i & 127;
            qsm[r][col] = qbase[(size_t)r * HW + n0 + ch0 + col];
            ksm[r][col] = kbase[(size_t)r * HW + n0 + ch0 + col];
        }
        __syncthreads();
#pragma unroll 4
        for (int j = 0; j < 128; j++) {
            float qv = qsm[c][j];
            float kv = ksm[d][j];
            acc += qv * kv;
            ssq += qv * qv;
            ssk += kv * kv;
        }
    }
    atomicAdd(&g_S[t][b][h][c * HD + d], acc);
    if (d == 0) atomicAdd(&g_qss[t][b][h][c], ssq);
    if (c == 0) atomicAdd(&g_kss[t][b][h][d], ssk);
}

// ---------------- K4: scale + softmax + M = wproj @ blockdiag(attn) ----------------
__global__ void k4_softmax_M(const float* __restrict__ wproj,
                             const float* __restrict__ temp)
{
    int t = blockIdx.x >> 3, b = blockIdx.x & 7;
    __shared__ float attn[C_IN][HD + 1];   // [h*24+i][j]
    __shared__ float invq[C_IN], invk[C_IN];

    int tid = threadIdx.x;                 // 192
    {
        int h = tid / HD, c = tid % HD;
        invq[tid] = 1.f / fmaxf(sqrtf(g_qss[t][b][h][c]), 1e-12f);
        invk[tid] = 1.f / fmaxf(sqrtf(g_kss[t][b][h][c]), 1e-12f);
    }
    __syncthreads();
    {
        int h = tid / HD, c = tid % HD;
        float tp = temp[h];
        float iq = invq[tid];
        float row[HD];
        float mx = -1e30f;
#pragma unroll
        for (int d = 0; d < HD; d++) {
            float v = g_S[t][b][h][c * HD + d] * iq * invk[h * HD + d] * tp;
            row[d] = v;
            mx = fmaxf(mx, v);
        }
        float sum = 0.f;
#pragma unroll
        for (int d = 0; d < HD; d++) { row[d] = expf(row[d] - mx); sum += row[d]; }
        float inv = 1.f / sum;
#pragma unroll
        for (int d = 0; d < HD; d++) attn[tid][d] = row[d] * inv;
    }
    __syncthreads();

    // M[o][h*24+j] = sum_i wproj[o][h*24+i] * attn[h*24+i][j]
    int o = tid;
    const float* wp = wproj + (size_t)o * C_IN;
    float* Mrow = &g_M[t][b][(size_t)o * C_IN];
    for (int h = 0; h < HEADS; h++) {
        float wreg[HD];
#pragma unroll
        for (int i = 0; i < HD; i++) wreg[i] = wp[h * HD + i];
#pragma unroll
        for (int j = 0; j < HD; j++) {
            float s = 0.f;
#pragma unroll
            for (int i = 0; i < HD; i++) s += wreg[i] * attn[h * HD + i][j];
            Mrow[h * HD + j] = s;
        }
    }
}

// ---------------- K5: out = M(192x192) @ V(192xHW), per (t,b), writes d_out ----------------
__global__ void k5_out(float* __restrict__ out)
{
    int z = blockIdx.z;                    // t*8+b ; v stream == t
    const float* A = g_M[z >> 3][z & 7];
    const float* V = g_qkv[z] + (size_t)(2 * C_IN) * HW;
    float* C = out + (size_t)z * C_IN * HW;
    gemm_64x128(A, V, C, blockIdx.y * 64, blockIdx.x * 128);
}

// ---------------- launch ----------------
extern "C" void kernel_launch(void* const* d_in, const int* in_sizes, int n_in,
                              void* d_out, int out_size)
{
    const float* rgb   = (const float*)d_in[0];
    const float* ir    = (const float*)d_in[1];
    const float* wqkv  = (const float*)d_in[2];
    const float* wdw   = (const float*)d_in[3];
    const float* wproj = (const float*)d_in[4];
    const float* temp  = (const float*)d_in[5];
    float* out = (float*)d_out;

    k0_zero<<<288, 256>>>();

    dim3 g1(HW / 128, C3 / 64, 16);
    k1_qkv<<<g1, 256>>>(rgb, ir, wqkv);

    dim3 g2(HW / 256, C3, 16);
    k2_dw<<<g2, 256>>>(wdw);

    dim3 g3(16, NB * HEADS, 2);
    k3_gram<<<g3, 576>>>();

    k4_softmax_M<<<16, 192>>>(wproj, temp);

    dim3 g5(HW / 128, C_IN / 64, 16);
    k5_out<<<g5, 256>>>(out);
}

// round 2
// speedup vs baseline: 1.8131x; 1.8131x over previous
#include <cuda_runtime.h>
#include <math.h>

// ---------------- problem constants ----------------
#define HW     16384      // 128*128
#define WIMG   128
#define C_IN   192
#define C3     576        // 3*C_IN
#define NB     8          // batch
#define HEADS  8
#define HD     24         // C_IN / HEADS

// ---------------- scratch (static device memory; no allocs) ----------------
__device__ float g_y  [16][C3 * HW];   // after 1x1 qkv conv
__device__ float g_qkv[16][C3 * HW];   // after depthwise 3x3
__device__ float g_S  [2][NB][HEADS][HD * HD];
__device__ float g_qss[2][NB][HEADS][HD];
__device__ float g_kss[2][NB][HEADS][HD];
__device__ float g_M  [2][NB][C_IN * C_IN];

// ---------------- K0: zero atomic accumulators ----------------
__global__ void k0_zero() {
    int idx = blockIdx.x * 256 + threadIdx.x;
    const int nS = 2 * NB * HEADS * HD * HD;     // 73728
    const int nN = 2 * NB * HEADS * HD;          // 3072
    if (idx < nS) (&g_S[0][0][0][0])[idx] = 0.f;
    if (idx < nN) {
        (&g_qss[0][0][0][0])[idx] = 0.f;
        (&g_kss[0][0][0][0])[idx] = 0.f;
    }
}

// ---------------- 64x256 double-buffered SGEMM tile ----------------
// C[m0:m0+64, n0:n0+256] = A[64 rows, 192] * B[192, HW-stride]
// A row-major stride 192; B row stride HW. 256 threads, 8x8 per thread.
__device__ __forceinline__ void gemm_64x256(
    const float* __restrict__ A,
    const float* __restrict__ Bm,
    float* __restrict__ C,
    int m0, int n0)
{
    __shared__ float As[2][16][68];     // transposed, padded (2-way STS only)
    __shared__ float Bs[2][16][256];

    const int tid = threadIdx.x;
    // global A load: each thread one float4 along k
    const int am = tid >> 2;            // 0..63
    const int ak = (tid & 3) * 4;       // 0,4,8,12
    // global B load: 4 float4 per thread, lane-contiguous within 64-word groups
    const int bk = tid >> 4;            // 0..15
    const int bn = (tid & 15) * 4;      // 0..60
    // compute mapping: A-frag broadcast per warp, B-frag conflict-free
    const int tm = (tid >> 5) * 8;      // 0..56 (constant within warp)
    const int tn = (tid & 31) * 4;      // 0..124 ; second half at +128

    const float* Aptr = A  + (size_t)(m0 + am) * 192 + ak;
    const float* Bptr = Bm + (size_t)bk * HW + n0 + bn;

    float4 areg;
    float4 breg0, breg1, breg2, breg3;

    // prologue: k-step 0
    areg  = *(const float4*)Aptr;
    breg0 = *(const float4*)(Bptr);
    breg1 = *(const float4*)(Bptr + 64);
    breg2 = *(const float4*)(Bptr + 128);
    breg3 = *(const float4*)(Bptr + 192);
    As[0][ak + 0][am] = areg.x;
    As[0][ak + 1][am] = areg.y;
    As[0][ak + 2][am] = areg.z;
    As[0][ak + 3][am] = areg.w;
    *(float4*)&Bs[0][bk][bn      ] = breg0;
    *(float4*)&Bs[0][bk][bn +  64] = breg1;
    *(float4*)&Bs[0][bk][bn + 128] = breg2;
    *(float4*)&Bs[0][bk][bn + 192] = breg3;
    __syncthreads();

    float acc[8][8];
#pragma unroll
    for (int i = 0; i < 8; i++)
#pragma unroll
        for (int j = 0; j < 8; j++) acc[i][j] = 0.f;

    int buf = 0;
    for (int ks = 0; ks < 12; ks++) {
        if (ks < 11) {
            const float* Ap = Aptr + (ks + 1) * 16;
            const float* Bp = Bptr + (size_t)(ks + 1) * 16 * HW;
            areg  = *(const float4*)Ap;
            breg0 = *(const float4*)(Bp);
            breg1 = *(const float4*)(Bp + 64);
            breg2 = *(const float4*)(Bp + 128);
            breg3 = *(const float4*)(Bp + 192);
        }
#pragma unroll
        for (int kk = 0; kk < 16; kk++) {
            float4 a0 = *(const float4*)&As[buf][kk][tm];
            float4 a1 = *(const float4*)&As[buf][kk][tm + 4];
            float4 b0 = *(const float4*)&Bs[buf][kk][tn];
            float4 b1 = *(const float4*)&Bs[buf][kk][tn + 128];
            float av[8] = {a0.x, a0.y, a0.z, a0.w, a1.x, a1.y, a1.z, a1.w};
            float bv[8] = {b0.x, b0.y, b0.z, b0.w, b1.x, b1.y, b1.z, b1.w};
#pragma unroll
            for (int i = 0; i < 8; i++)
#pragma unroll
                for (int j = 0; j < 8; j++)
                    acc[i][j] += av[i] * bv[j];
        }
        if (ks < 11) {
            int nb = buf ^ 1;
            As[nb][ak + 0][am] = areg.x;
            As[nb][ak + 1][am] = areg.y;
            As[nb][ak + 2][am] = areg.z;
            As[nb][ak + 3][am] = areg.w;
            *(float4*)&Bs[nb][bk][bn      ] = breg0;
            *(float4*)&Bs[nb][bk][bn +  64] = breg1;
            *(float4*)&Bs[nb][bk][bn + 128] = breg2;
            *(float4*)&Bs[nb][bk][bn + 192] = breg3;
            __syncthreads();
            buf = nb;
        }
    }

#pragma unroll
    for (int i = 0; i < 8; i++) {
        float* Crow = C + (size_t)(m0 + tm + i) * HW + n0;
        *(float4*)&Crow[tn      ] = make_float4(acc[i][0], acc[i][1], acc[i][2], acc[i][3]);
        *(float4*)&Crow[tn + 128] = make_float4(acc[i][4], acc[i][5], acc[i][6], acc[i][7]);
    }
}

// ---------------- K1: 1x1 qkv conv ----------------
__global__ void __launch_bounds__(256, 2)
k1_qkv(const float* __restrict__ rgb,
       const float* __restrict__ ir,
       const float* __restrict__ wqkv)
{
    int z = blockIdx.z;                   // s*8+b
    int s = z >> 3, b = z & 7;
    const float* x = (s ? ir : rgb) + (size_t)b * C_IN * HW;
    gemm_64x256(wqkv, x, g_y[z], blockIdx.y * 64, blockIdx.x * 256);
}

// ---------------- K2: depthwise 3x3 SAME, 4 outputs/thread ----------------
__global__ void k2_dw(const float* __restrict__ wdw)
{
    int z  = blockIdx.z;
    int ch = blockIdx.y;
    int n  = blockIdx.x * 1024 + threadIdx.x * 4;
    const float* yin = g_y[z]  + (size_t)ch * HW;
    float*       out = g_qkv[z] + (size_t)ch * HW;

    const float* w = wdw + ch * 9;
    float wr[3][3];
#pragma unroll
    for (int i = 0; i < 9; i++) wr[i / 3][i % 3] = w[i];

    int yy = n >> 7, xx = n & 127;
    bool xm = (xx > 0), xp = (xx < 124);
    float o0 = 0.f, o1 = 0.f, o2 = 0.f, o3 = 0.f;

#pragma unroll
    for (int r = 0; r < 3; r++) {
        int ry = yy + r - 1;
        if (ry < 0 || ry >= WIMG) continue;
        const float* row = yin + (size_t)ry * WIMG;
        float4 cv = *(const float4*)&row[xx];
        float lft = xm ? row[xx - 1] : 0.f;
        float rgt = xp ? row[xx + 4] : 0.f;
        float w0 = wr[r][0], w1 = wr[r][1], w2 = wr[r][2];
        o0 += w0 * lft  + w1 * cv.x + w2 * cv.y;
        o1 += w0 * cv.x + w1 * cv.y + w2 * cv.z;
        o2 += w0 * cv.y + w1 * cv.z + w2 * cv.w;
        o3 += w0 * cv.z + w1 * cv.w + w2 * rgt;
    }
    *(float4*)&out[n] = make_float4(o0, o1, o2, o3);
}

// ---------------- K3: channel Gram + sumsq (float4, dedup) ----------------
// t=0: q = iq (s=1), k = rk (s=0);  t=1: q = rq (s=0), k = ik (s=1)
__global__ void k3_gram()
{
    int t  = blockIdx.z;
    int bh = blockIdx.y;
    int b = bh >> 3, h = bh & 7;
    int n0 = blockIdx.x * 1024;

    int qs = (t == 0) ? 1 : 0;
    int kstream = 1 - qs;
    const float* qbase = g_qkv[qs * 8 + b]      + (size_t)(h * HD) * HW + n0;
    const float* kbase = g_qkv[kstream * 8 + b] + (size_t)(C_IN + h * HD) * HW + n0;

    __shared__ float qsm[HD][140];
    __shared__ float ksm[HD][140];

    int tid = threadIdx.x;                // 576
    int c = tid / HD, d = tid - c * HD;
    bool do_q = (d == 0), do_k = (c == 0);

    float acc = 0.f, ssq = 0.f, ssk = 0.f;
    for (int ch0 = 0; ch0 < 1024; ch0 += 128) {
        __syncthreads();
        for (int i = tid; i < 2 * HD * 32; i += 576) {   // 1536 float4s
            int arr = (i >= 768);
            int li  = arr ? (i - 768) : i;
            int r   = li >> 5;
            int c4  = (li & 31) * 4;
            const float* src = arr ? kbase : qbase;
            float4 v = *(const float4*)&src[(size_t)r * HW + ch0 + c4];
            if (arr) *(float4*)&ksm[r][c4] = v;
            else     *(float4*)&qsm[r][c4] = v;
        }
        __syncthreads();
#pragma unroll 8
        for (int j = 0; j < 128; j += 4) {
            float4 q4 = *(const float4*)&qsm[c][j];
            float4 k4 = *(const float4*)&ksm[d][j];
            acc += q4.x * k4.x + q4.y * k4.y + q4.z * k4.z + q4.w * k4.w;
            if (do_q) ssq += q4.x * q4.x + q4.y * q4.y + q4.z * q4.z + q4.w * q4.w;
            if (do_k) ssk += k4.x * k4.x + k4.y * k4.y + k4.z * k4.z + k4.w * k4.w;
        }
    }
    atomicAdd(&g_S[t][b][h][c * HD + d], acc);
    if (do_q) atomicAdd(&g_qss[t][b][h][c], ssq);
    if (do_k) atomicAdd(&g_kss[t][b][h][d], ssk);
}

// ---------------- K4: scale + softmax + M = wproj @ blockdiag(attn) ----------------
__global__ void k4_softmax_M(const float* __restrict__ wproj,
                             const float* __restrict__ temp)
{
    int t = blockIdx.x >> 3, b = blockIdx.x & 7;
    __shared__ float attn[C_IN][HD + 1];
    __shared__ float invq[C_IN], invk[C_IN];

    int tid = threadIdx.x;                 // 192
    {
        int h = tid / HD, c = tid % HD;
        invq[tid] = 1.f / fmaxf(sqrtf(g_qss[t][b][h][c]), 1e-12f);
        invk[tid] = 1.f / fmaxf(sqrtf(g_kss[t][b][h][c]), 1e-12f);
    }
    __syncthreads();
    {
        int h = tid / HD, c = tid % HD;
        float tp = temp[h];
        float iq = invq[tid];
        float row[HD];
        float mx = -1e30f;
#pragma unroll
        for (int d = 0; d < HD; d++) {
            float v = g_S[t][b][h][c * HD + d] * iq * invk[h * HD + d] * tp;
            row[d] = v;
            mx = fmaxf(mx, v);
        }
        float sum = 0.f;
#pragma unroll
        for (int d = 0; d < HD; d++) { row[d] = expf(row[d] - mx); sum += row[d]; }
        float inv = 1.f / sum;
#pragma unroll
        for (int d = 0; d < HD; d++) attn[tid][d] = row[d] * inv;
    }
    __syncthreads();

    int o = tid;
    const float* wp = wproj + (size_t)o * C_IN;
    float* Mrow = &g_M[t][b][(size_t)o * C_IN];
    for (int h = 0; h < HEADS; h++) {
        float wreg[HD];
#pragma unroll
        for (int i = 0; i < HD; i++) wreg[i] = wp[h * HD + i];
#pragma unroll
        for (int j = 0; j < HD; j++) {
            float s = 0.f;
#pragma unroll
            for (int i = 0; i < HD; i++) s += wreg[i] * attn[h * HD + i][j];
            Mrow[h * HD + j] = s;
        }
    }
}

// ---------------- K5: out = M(192x192) @ V(192xHW) ----------------
__global__ void __launch_bounds__(256, 2)
k5_out(float* __restrict__ out)
{
    int z = blockIdx.z;
    const float* A = g_M[z >> 3][z & 7];
    const float* V = g_qkv[z] + (size_t)(2 * C_IN) * HW;
    float* C = out + (size_t)z * C_IN * HW;
    gemm_64x256(A, V, C, blockIdx.y * 64, blockIdx.x * 256);
}

// ---------------- launch ----------------
extern "C" void kernel_launch(void* const* d_in, const int* in_sizes, int n_in,
                              void* d_out, int out_size)
{
    const float* rgb   = (const float*)d_in[0];
    const float* ir    = (const float*)d_in[1];
    const float* wqkv  = (const float*)d_in[2];
    const float* wdw   = (const float*)d_in[3];
    const float* wproj = (const float*)d_in[4];
    const float* temp  = (const float*)d_in[5];
    float* out = (float*)d_out;

    k0_zero<<<288, 256>>>();

    dim3 g1(HW / 256, C3 / 64, 16);
    k1_qkv<<<g1, 256>>>(rgb, ir, wqkv);

    dim3 g2(HW / 1024, C3, 16);
    k2_dw<<<g2, 256>>>(wdw);

    dim3 g3(16, NB * HEADS, 2);
    k3_gram<<<g3, 576>>>();

    k4_softmax_M<<<16, 192>>>(wproj, temp);

    dim3 g5(HW / 256, C_IN / 64, 16);
    k5_out<<<g5, 256>>>(out);
}

// round 4
// speedup vs baseline: 2.9234x; 1.6124x over previous
#include <cuda_runtime.h>
#include <cstdint>
#include <math.h>

// ---------------- problem constants ----------------
#define HW     16384      // 128*128
#define WIMG   128
#define C_IN   192
#define C3     576        // 3*C_IN
#define NB     8          // batch
#define HEADS  8
#define HD     24         // C_IN / HEADS

// ---------------- scratch ----------------
__device__ float g_y  [16][C3 * HW];
__device__ float g_qkv[16][C3 * HW];
__device__ float g_S  [2][NB][HEADS][HD * HD];
__device__ float g_qss[2][NB][HEADS][HD];
__device__ float g_kss[2][NB][HEADS][HD];
__device__ float g_M  [2][NB][C_IN * C_IN];

// ---------------- K0: zero atomic accumulators ----------------
__global__ void k0_zero() {
    int idx = blockIdx.x * 256 + threadIdx.x;
    const int nS = 2 * NB * HEADS * HD * HD;
    const int nN = 2 * NB * HEADS * HD;
    if (idx < nS) (&g_S[0][0][0][0])[idx] = 0.f;
    if (idx < nN) {
        (&g_qss[0][0][0][0])[idx] = 0.f;
        (&g_kss[0][0][0][0])[idx] = 0.f;
    }
}

// ---------------- tf32 helpers ----------------
__device__ __forceinline__ uint32_t f2tf32(float x) {
    uint32_t r;
    asm("cvt.rna.tf32.f32 %0, %1;" : "=r"(r) : "f"(x));
    return r;
}
__device__ __forceinline__ void mma_16x8x8(float* c, const uint32_t* a, const uint32_t* b) {
    asm volatile(
        "mma.sync.aligned.m16n8k8.row.col.f32.tf32.tf32.f32 "
        "{%0,%1,%2,%3}, {%4,%5,%6,%7}, {%8,%9}, {%0,%1,%2,%3};"
        : "+f"(c[0]), "+f"(c[1]), "+f"(c[2]), "+f"(c[3])
        : "r"(a[0]), "r"(a[1]), "r"(a[2]), "r"(a[3]), "r"(b[0]), "r"(b[1]));
}

// ---------------- mma.sync tf32 GEMM: C[m0:m0+128, n0:n0+128] = A(.,192) @ B(192,HW) ----------------
// A row-major stride 192; B row stride HW; C row stride HW. 256 threads (8 warps).
// Warp grid 4(M) x 2(N): warp tile 32x64 = 2x8 m16n8k8 tiles. BK=16, double-buffered.
__device__ __forceinline__ void gemm_mma_128x128(
    const float* __restrict__ A, const float* __restrict__ B, float* __restrict__ C,
    int m0, int n0)
{
    __shared__ uint32_t As[2][128][20];   // [m][k], stride 20: conflict-free
    __shared__ uint32_t Bs[2][16][136];   // [k][n], stride 136: conflict-free

    const int tid  = threadIdx.x;
    const int wid  = tid >> 5;
    const int lane = tid & 31;
    const int warp_m = wid & 3;           // 0..3 -> 32 rows each
    const int warp_n = wid >> 2;          // 0..1 -> 64 cols each
    const int lr = lane >> 2;             // 0..7
    const int lc = lane & 3;              // 0..3

    // global load indices
    const int ar0 = tid >> 2;             // 0..63 (and +64)
    const int akq = (tid & 3) * 4;        // 0,4,8,12
    const int bkr = tid >> 4;             // 0..15
    const int bnq = (tid & 15) * 4;       // 0..60 (and +64)

    const float* Ap = A + (size_t)(m0 + ar0) * 192 + akq;
    const float* Bp = B + (size_t)bkr * HW + n0 + bnq;

    float4 a0g, a1g, b0g, b1g;

    // prologue: chunk 0
    a0g = *(const float4*)Ap;
    a1g = *(const float4*)(Ap + 64 * 192);
    b0g = *(const float4*)Bp;
    b1g = *(const float4*)(Bp + 64);
    {
        uint32_t* d0 = &As[0][ar0][akq];
        d0[0] = f2tf32(a0g.x); d0[1] = f2tf32(a0g.y); d0[2] = f2tf32(a0g.z); d0[3] = f2tf32(a0g.w);
        uint32_t* d1 = &As[0][ar0 + 64][akq];
        d1[0] = f2tf32(a1g.x); d1[1] = f2tf32(a1g.y); d1[2] = f2tf32(a1g.z); d1[3] = f2tf32(a1g.w);
        uint32_t* e0 = &Bs[0][bkr][bnq];
        e0[0] = f2tf32(b0g.x); e0[1] = f2tf32(b0g.y); e0[2] = f2tf32(b0g.z); e0[3] = f2tf32(b0g.w);
        uint32_t* e1 = &Bs[0][bkr][bnq + 64];
        e1[0] = f2tf32(b1g.x); e1[1] = f2tf32(b1g.y); e1[2] = f2tf32(b1g.z); e1[3] = f2tf32(b1g.w);
    }
    __syncthreads();

    float acc[2][8][4];
#pragma unroll
    for (int i = 0; i < 2; i++)
#pragma unroll
        for (int j = 0; j < 8; j++)
#pragma unroll
            for (int q = 0; q < 4; q++) acc[i][j][q] = 0.f;

    int buf = 0;
    for (int ch = 0; ch < 12; ch++) {
        if (ch < 11) {
            const float* Apn = Ap + (ch + 1) * 16;
            const float* Bpn = Bp + (size_t)(ch + 1) * 16 * HW;
            a0g = *(const float4*)Apn;
            a1g = *(const float4*)(Apn + 64 * 192);
            b0g = *(const float4*)Bpn;
            b1g = *(const float4*)(Bpn + 64);
        }
#pragma unroll
        for (int kst = 0; kst < 2; kst++) {
            const int k0 = kst * 8;
            uint32_t afr[2][4];
#pragma unroll
            for (int mt = 0; mt < 2; mt++) {
                int rb = warp_m * 32 + mt * 16 + lr;
                afr[mt][0] = As[buf][rb][k0 + lc];
                afr[mt][1] = As[buf][rb + 8][k0 + lc];
                afr[mt][2] = As[buf][rb][k0 + 4 + lc];
                afr[mt][3] = As[buf][rb + 8][k0 + 4 + lc];
            }
#pragma unroll
            for (int nt = 0; nt < 8; nt++) {
                uint32_t bfr[2];
                int nn = warp_n * 64 + nt * 8 + lr;
                bfr[0] = Bs[buf][k0 + lc][nn];
                bfr[1] = Bs[buf][k0 + 4 + lc][nn];
                mma_16x8x8(acc[0][nt], afr[0], bfr);
                mma_16x8x8(acc[1][nt], afr[1], bfr);
            }
        }
        if (ch < 11) {
            int nb = buf ^ 1;
            uint32_t* d0 = &As[nb][ar0][akq];
            d0[0] = f2tf32(a0g.x); d0[1] = f2tf32(a0g.y); d0[2] = f2tf32(a0g.z); d0[3] = f2tf32(a0g.w);
            uint32_t* d1 = &As[nb][ar0 + 64][akq];
            d1[0] = f2tf32(a1g.x); d1[1] = f2tf32(a1g.y); d1[2] = f2tf32(a1g.z); d1[3] = f2tf32(a1g.w);
            uint32_t* e0 = &Bs[nb][bkr][bnq];
            e0[0] = f2tf32(b0g.x); e0[1] = f2tf32(b0g.y); e0[2] = f2tf32(b0g.z); e0[3] = f2tf32(b0g.w);
            uint32_t* e1 = &Bs[nb][bkr][bnq + 64];
            e1[0] = f2tf32(b1g.x); e1[1] = f2tf32(b1g.y); e1[2] = f2tf32(b1g.z); e1[3] = f2tf32(b1g.w);
            __syncthreads();
            buf = nb;
        }
    }

    // epilogue: c0/c1 at (row, 2*lc), c2/c3 at row+8
#pragma unroll
    for (int mt = 0; mt < 2; mt++) {
        int row = m0 + warp_m * 32 + mt * 16 + lr;
#pragma unroll
        for (int nt = 0; nt < 8; nt++) {
            int col = n0 + warp_n * 64 + nt * 8 + lc * 2;
            float* p0 = C + (size_t)row * HW + col;
            float* p1 = C + (size_t)(row + 8) * HW + col;
            *(float2*)p0 = make_float2(acc[mt][nt][0], acc[mt][nt][1]);
            *(float2*)p1 = make_float2(acc[mt][nt][2], acc[mt][nt][3]);
        }
    }
}

// ---------------- K1: 1x1 qkv conv via mma ----------------
__global__ void __launch_bounds__(256)
k1_qkv(const float* __restrict__ rgb, const float* __restrict__ ir,
       const float* __restrict__ wqkv)
{
    int z = blockIdx.z, s = z >> 3, b = z & 7;
    int m0 = blockIdx.y * 128;
    if (m0 > C3 - 128) m0 = C3 - 128;    // overlap tile: identical double-writes
    const float* x = (s ? ir : rgb) + (size_t)b * C_IN * HW;
    gemm_mma_128x128(wqkv, x, g_y[z], m0, blockIdx.x * 128);
}

// ---------------- K5: out = M @ V via mma ----------------
__global__ void __launch_bounds__(256)
k5_out(float* __restrict__ out)
{
    int z = blockIdx.z;
    const float* A = g_M[z >> 3][z & 7];
    const float* V = g_qkv[z] + (size_t)(2 * C_IN) * HW;
    float* C = out + (size_t)z * C_IN * HW;
    int m0 = blockIdx.y * 64;            // 0 or 64: covers 192 rows w/ overlap
    gemm_mma_128x128(A, V, C, m0, blockIdx.x * 128);
}

// ---------------- K2: depthwise 3x3 SAME, 4 outputs/thread ----------------
__global__ void k2_dw(const float* __restrict__ wdw)
{
    int z  = blockIdx.z;
    int ch = blockIdx.y;
    int n  = blockIdx.x * 1024 + threadIdx.x * 4;
    const float* yin = g_y[z]  + (size_t)ch * HW;
    float*       out = g_qkv[z] + (size_t)ch * HW;

    const float* w = wdw + ch * 9;
    float wr[3][3];
#pragma unroll
    for (int i = 0; i < 9; i++) wr[i / 3][i % 3] = w[i];

    int yy = n >> 7, xx = n & 127;
    bool xm = (xx > 0), xp = (xx < 124);
    float o0 = 0.f, o1 = 0.f, o2 = 0.f, o3 = 0.f;
#pragma unroll
    for (int r = 0; r < 3; r++) {
        int ry = yy + r - 1;
        if (ry < 0 || ry >= WIMG) continue;
        const float* row = yin + (size_t)ry * WIMG;
        float4 cv = *(const float4*)&row[xx];
        float lft = xm ? row[xx - 1] : 0.f;
        float rgt = xp ? row[xx + 4] : 0.f;
        float w0 = wr[r][0], w1 = wr[r][1], w2 = wr[r][2];
        o0 += w0 * lft  + w1 * cv.x + w2 * cv.y;
        o1 += w0 * cv.x + w1 * cv.y + w2 * cv.z;
        o2 += w0 * cv.y + w1 * cv.z + w2 * cv.w;
        o3 += w0 * cv.z + w1 * cv.w + w2 * rgt;
    }
    *(float4*)&out[n] = make_float4(o0, o1, o2, o3);
}

// ---------------- K3: channel Gram + sumsq ----------------
__global__ void k3_gram()
{
    int t  = blockIdx.z;
    int bh = blockIdx.y;
    int b = bh >> 3, h = bh & 7;
    int n0 = blockIdx.x * 1024;

    int qs = (t == 0) ? 1 : 0;
    int kstream = 1 - qs;
    const float* qbase = g_qkv[qs * 8 + b]      + (size_t)(h * HD) * HW + n0;
    const float* kbase = g_qkv[kstream * 8 + b] + (size_t)(C_IN + h * HD) * HW + n0;

    __shared__ float qsm[HD][140];
    __shared__ float ksm[HD][140];

    int tid = threadIdx.x;                // 576
    int c = tid / HD, d = tid - c * HD;
    bool do_q = (d == 0), do_k = (c == 0);

    float acc = 0.f, ssq = 0.f, ssk = 0.f;
    for (int ch0 = 0; ch0 < 1024; ch0 += 128) {
        __syncthreads();
        for (int i = tid; i < 2 * HD * 32; i += 576) {
            int arr = (i >= 768);
            int li  = arr ? (i - 768) : i;
            int r   = li >> 5;
            int c4  = (li & 31) * 4;
            const float* src = arr ? kbase : qbase;
            float4 v = *(const float4*)&src[(size_t)r * HW + ch0 + c4];
            if (arr) *(float4*)&ksm[r][c4] = v;
            else     *(float4*)&qsm[r][c4] = v;
        }
        __syncthreads();
#pragma unroll 8
        for (int j = 0; j < 128; j += 4) {
            float4 q4 = *(const float4*)&qsm[c][j];
            float4 k4 = *(const float4*)&ksm[d][j];
            acc += q4.x * k4.x + q4.y * k4.y + q4.z * k4.z + q4.w * k4.w;
            if (do_q) ssq += q4.x * q4.x + q4.y * q4.y + q4.z * q4.z + q4.w * q4.w;
            if (do_k) ssk += k4.x * k4.x + k4.y * k4.y + k4.z * k4.z + k4.w * k4.w;
        }
    }
    atomicAdd(&g_S[t][b][h][c * HD + d], acc);
    if (do_q) atomicAdd(&g_qss[t][b][h][c], ssq);
    if (do_k) atomicAdd(&g_kss[t][b][h][d], ssk);
}

// ---------------- K4: scale + softmax + M = wproj @ blockdiag(attn) ----------------
__global__ void k4_softmax_M(const float* __restrict__ wproj,
                             const float* __restrict__ temp)
{
    int t = blockIdx.x >> 3, b = blockIdx.x & 7;
    __shared__ float attn[C_IN][HD + 1];
    __shared__ float invq[C_IN], invk[C_IN];

    int tid = threadIdx.x;                 // 192
    {
        int h = tid / HD, c = tid % HD;
        invq[tid] = 1.f / fmaxf(sqrtf(g_qss[t][b][h][c]), 1e-12f);
        invk[tid] = 1.f / fmaxf(sqrtf(g_kss[t][b][h][c]), 1e-12f);
    }
    __syncthreads();
    {
        int h = tid / HD, c = tid % HD;
        float tp = temp[h];
        float iq = invq[tid];
        float row[HD];
        float mx = -1e30f;
#pragma unroll
        for (int d = 0; d < HD; d++) {
            float v = g_S[t][b][h][c * HD + d] * iq * invk[h * HD + d] * tp;
            row[d] = v;
            mx = fmaxf(mx, v);
        }
        float sum = 0.f;
#pragma unroll
        for (int d = 0; d < HD; d++) { row[d] = expf(row[d] - mx); sum += row[d]; }
        float inv = 1.f / sum;
#pragma unroll
        for (int d = 0; d < HD; d++) attn[tid][d] = row[d] * inv;
    }
    __syncthreads();

    int o = tid;
    const float* wp = wproj + (size_t)o * C_IN;
    float* Mrow = &g_M[t][b][(size_t)o * C_IN];
    for (int h = 0; h < HEADS; h++) {
        float wreg[HD];
#pragma unroll
        for (int i = 0; i < HD; i++) wreg[i] = wp[h * HD + i];
#pragma unroll
        for (int j = 0; j < HD; j++) {
            float s = 0.f;
#pragma unroll
            for (int i = 0; i < HD; i++) s += wreg[i] * attn[h * HD + i][j];
            Mrow[h * HD + j] = s;
        }
    }
}

// ---------------- launch ----------------
extern "C" void kernel_launch(void* const* d_in, const int* in_sizes, int n_in,
                              void* d_out, int out_size)
{
    const float* rgb   = (const float*)d_in[0];
    const float* ir    = (const float*)d_in[1];
    const float* wqkv  = (const float*)d_in[2];
    const float* wdw   = (const float*)d_in[3];
    const float* wproj = (const float*)d_in[4];
    const float* temp  = (const float*)d_in[5];
    float* out = (float*)d_out;

    k0_zero<<<288, 256>>>();

    dim3 g1(HW / 128, 5, 16);     // m0: 0,128,256,384,448(clamped)
    k1_qkv<<<g1, 256>>>(rgb, ir, wqkv);

    dim3 g2(HW / 1024, C3, 16);
    k2_dw<<<g2, 256>>>(wdw);

    dim3 g3(16, NB * HEADS, 2);
    k3_gram<<<g3, 576>>>();

    k4_softmax_M<<<16, 192>>>(wproj, temp);

    dim3 g5(HW / 128, 2, 16);     // m0: 0, 64 (overlap)
    k5_out<<<g5, 256>>>(out);
}